// round 6
// baseline (speedup 1.0000x reference)
#include <cuda_runtime.h>
#include <cuda_fp16.h>
#include <cstdint>

// ---------------- problem constants ----------------
#define Bv   2
#define Hv   16
#define Sv   2048
#define Dv   64
#define TQ   128           // query rows per CTA (8 warps x 16 rows)
#define TK   64            // keys per tile
#define NT   (Sv / TK)     // 32 tiles
#define NTH  256

// ---------------- helpers ----------------
__device__ __forceinline__ uint32_t smem_u32(const void* p) {
    uint32_t a;
    asm("{ .reg .u64 t; cvta.to.shared.u64 t, %1; cvt.u32.u64 %0, t; }" : "=r"(a) : "l"(p));
    return a;
}
__device__ __forceinline__ uint32_t f2h2(float x, float y) {
    __half2 h = __floats2half2_rn(x, y);
    return *reinterpret_cast<uint32_t*>(&h);
}
__device__ __forceinline__ void ldsm4(uint32_t& r0, uint32_t& r1, uint32_t& r2, uint32_t& r3, uint32_t a) {
    asm volatile("ldmatrix.sync.aligned.m8n8.x4.shared.b16 {%0,%1,%2,%3}, [%4];"
                 : "=r"(r0), "=r"(r1), "=r"(r2), "=r"(r3) : "r"(a));
}
__device__ __forceinline__ void ldsm4t(uint32_t& r0, uint32_t& r1, uint32_t& r2, uint32_t& r3, uint32_t a) {
    asm volatile("ldmatrix.sync.aligned.m8n8.x4.trans.shared.b16 {%0,%1,%2,%3}, [%4];"
                 : "=r"(r0), "=r"(r1), "=r"(r2), "=r"(r3) : "r"(a));
}
__device__ __forceinline__ void mma16816(float* c, const uint32_t* a, uint32_t b0, uint32_t b1) {
    asm volatile(
        "mma.sync.aligned.m16n8k16.row.col.f32.f16.f16.f32 "
        "{%0,%1,%2,%3}, {%4,%5,%6,%7}, {%8,%9}, {%0,%1,%2,%3};"
        : "+f"(c[0]), "+f"(c[1]), "+f"(c[2]), "+f"(c[3])
        : "r"(a[0]), "r"(a[1]), "r"(a[2]), "r"(a[3]), "r"(b0), "r"(b1));
}
// SW128 swizzle for a [64 rows][128B] fp16 tile
__device__ __forceinline__ uint32_t swz(int row, int cb) {
    return (uint32_t)(row * 128 + (cb ^ ((row & 7) << 4)));
}
// key permutation: tile row p(n) for gmem key n within a 64-key tile.
// p5..p0 = n5 n4 n3<-n1? mapping: p = (n&0x30)|((n&0x02)<<2)|((n&0x0C)>>1)|(n&1)
__device__ __forceinline__ int kperm(int n) {
    return (n & 0x30) | ((n & 0x02) << 2) | ((n & 0x0C) >> 1) | (n & 0x01);
}
__device__ __forceinline__ void sts16(uint32_t a, uint32_t x, uint32_t y, uint32_t z, uint32_t w) {
    asm volatile("st.shared.v4.b32 [%0], {%1,%2,%3,%4};"
                 :: "r"(a), "r"(x), "r"(y), "r"(z), "r"(w) : "memory");
}

// ---------------- kernel ----------------
__global__ __launch_bounds__(NTH, 2)
void flashret_fp16_kernel(const float* __restrict__ q,
                          const float* __restrict__ k,
                          const float* __restrict__ v,
                          const float* __restrict__ mask,
                          float* __restrict__ out)
{
    // K/V fp16 tiles, double buffered, SW128-swizzled: 4 x 8KB = 32KB
    __shared__ __align__(1024) uint8_t smem[32768];
    const uint32_t sb = smem_u32(smem);
    const uint32_t KB0 = sb, KB1 = sb + 8192, VB0 = sb + 16384, VB1 = sb + 24576;

    const int tid  = threadIdx.x;
    const int warp = tid >> 5;
    const int lane = tid & 31;
    const int tq   = lane >> 2;        // fragment row group
    const int qd   = lane & 3;         // quad column
    const int R    = warp * 16;

    const int bh = blockIdx.y;
    const int qt = blockIdx.x;

    const size_t qrow = (size_t)bh * Sv + (size_t)qt * TQ + R + tq;
    const float* qlo = q + qrow * Dv;
    const float* qhi = qlo + 8 * Dv;
    const float* mlo = mask + qrow * (size_t)Sv;
    const float* mhi = mlo + (size_t)8 * Sv;
    float* olo = out + qrow * Dv;
    float* ohi = olo + 8 * Dv;
    const float* kg = k + (size_t)bh * Sv * Dv;
    const float* vg = v + (size_t)bh * Sv * Dv;

    // producer indices: thread handles gmem tile-rows n0, n0+32 (coalesced LDG),
    // stores them at permuted tile rows (swizzled)
    const int n0 = tid >> 3, pc0 = (tid & 7) * 8;
    const uint32_t so0 = swz(kperm(n0), pc0 * 2);
    const uint32_t so1 = swz(kperm(n0) + 32, pc0 * 2);   // kperm(n0+32)=kperm(n0)+32

    // ---- Q A-fragments straight from gmem ----
    uint32_t qa[4][4];
    #pragma unroll
    for (int kb = 0; kb < 4; ++kb) {
        float2 a0 = *(const float2*)(qlo + kb * 16 + 2 * qd);
        float2 a1 = *(const float2*)(qhi + kb * 16 + 2 * qd);
        float2 a2 = *(const float2*)(qlo + kb * 16 + 8 + 2 * qd);
        float2 a3 = *(const float2*)(qhi + kb * 16 + 8 + 2 * qd);
        qa[kb][0] = f2h2(a0.x, a0.y);
        qa[kb][1] = f2h2(a1.x, a1.y);
        qa[kb][2] = f2h2(a2.x, a2.y);
        qa[kb][3] = f2h2(a3.x, a3.y);
    }

    float o[8][4];
    #pragma unroll
    for (int j = 0; j < 8; ++j) { o[j][0] = o[j][1] = o[j][2] = o[j][3] = 0.0f; }
    float rlo = 0.0f, rhi = 0.0f;

    // ---- prologue: K/V tile 0 into buffer 0, mask tile 0 into regs ----
    {
        const float* kr0 = kg + n0 * Dv + pc0;
        const float* kr1 = kg + (n0 + 32) * Dv + pc0;
        const float* vr0 = vg + n0 * Dv + pc0;
        const float* vr1 = vg + (n0 + 32) * Dv + pc0;
        float4 f0 = *(const float4*)(kr0),     f1 = *(const float4*)(kr0 + 4);
        float4 f2 = *(const float4*)(kr1),     f3 = *(const float4*)(kr1 + 4);
        float4 g0 = *(const float4*)(vr0),     g1 = *(const float4*)(vr0 + 4);
        float4 g2 = *(const float4*)(vr1),     g3 = *(const float4*)(vr1 + 4);
        sts16(KB0 + so0, f2h2(f0.x,f0.y), f2h2(f0.z,f0.w), f2h2(f1.x,f1.y), f2h2(f1.z,f1.w));
        sts16(KB0 + so1, f2h2(f2.x,f2.y), f2h2(f2.z,f2.w), f2h2(f3.x,f3.y), f2h2(f3.z,f3.w));
        sts16(VB0 + so0, f2h2(g0.x,g0.y), f2h2(g0.z,g0.w), f2h2(g1.x,g1.y), f2h2(g1.z,g1.w));
        sts16(VB0 + so1, f2h2(g2.x,g2.y), f2h2(g2.z,g2.w), f2h2(g3.x,g3.y), f2h2(g3.z,g3.w));
    }
    // mask regs for current tile: float4 per jg, rows lo & hi
    float4 mcl[4], mch[4];
    {
        const float4* ml4 = (const float4*)mlo;
        const float4* mh4 = (const float4*)mhi;
        #pragma unroll
        for (int jg = 0; jg < 4; ++jg) {
            mcl[jg] = ml4[jg * 4 + qd];
            mch[jg] = mh4[jg * 4 + qd];
        }
    }
    __syncthreads();

    // ldmatrix lane-address components
    const int l7  = lane & 7;
    const int l15 = lane & 15;
    const int kha = ((lane >> 3) & 1) * 16;   // k-half for GEMM1 x4
    const int grp = lane >> 4;                // 0/1: second-block selector

    for (int kt = 0; kt < NT; ++kt) {
        const uint32_t KBc = (kt & 1) ? KB1 : KB0;
        const uint32_t VBc = (kt & 1) ? VB1 : VB0;
        const uint32_t KBn = (kt & 1) ? KB0 : KB1;
        const uint32_t VBn = (kt & 1) ? VB0 : VB1;
        const bool pf = (kt + 1) < NT;

        // ---- GEMM1: S(16x64) = Q @ K^T  (x4 ldsm: two k-blocks per load) ----
        float c[8][4];
        #pragma unroll
        for (int j = 0; j < 8; ++j) { c[j][0] = c[j][1] = c[j][2] = c[j][3] = 0.0f; }
        #pragma unroll
        for (int j = 0; j < 8; ++j) {
            #pragma unroll
            for (int kbp = 0; kbp < 2; ++kbp) {
                uint32_t b0, b1, b2, b3;
                ldsm4(b0, b1, b2, b3,
                      KBc + swz(8 * j + l7, (2 * kbp + grp) * 32 + kha));
                mma16816(c[j], qa[2 * kbp],     b0, b1);
                mma16816(c[j], qa[2 * kbp + 1], b2, b3);
            }
        }

        // prefetch next K tile (regs), hide behind mask phase
        float4 kf0, kf1, kf2, kf3;
        if (pf) {
            const float* kp = kg + (size_t)(kt + 1) * TK * Dv;
            kf0 = *(const float4*)(kp + n0 * Dv + pc0);
            kf1 = *(const float4*)(kp + n0 * Dv + pc0 + 4);
            kf2 = *(const float4*)(kp + (n0 + 32) * Dv + pc0);
            kf3 = *(const float4*)(kp + (n0 + 32) * Dv + pc0 + 4);
        }

        // ---- mask multiply + |.| + pack P A-frags (permuted-key layout) ----
        uint32_t pa[4][4];
        #pragma unroll
        for (int jg = 0; jg < 4; ++jg) {
            const int j0 = 2 * jg, j1 = j0 + 1;
            float4 a = mcl[jg], b = mch[jg];
            float p00 = c[j0][0] * a.x;
            float p01 = c[j0][1] * a.y;
            float p10 = c[j1][0] * a.z;
            float p11 = c[j1][1] * a.w;
            float q00 = c[j0][2] * b.x;
            float q01 = c[j0][3] * b.y;
            float q10 = c[j1][2] * b.z;
            float q11 = c[j1][3] * b.w;
            rlo += fabsf(p00) + fabsf(p01) + fabsf(p10) + fabsf(p11);
            rhi += fabsf(q00) + fabsf(q01) + fabsf(q10) + fabsf(q11);
            pa[jg][0] = f2h2(p00, p01);   // j0, rows lo
            pa[jg][1] = f2h2(q00, q01);   // j0, rows hi
            pa[jg][2] = f2h2(p10, p11);   // j1, rows lo
            pa[jg][3] = f2h2(q10, q11);   // j1, rows hi
        }

        // mask prefetch for next tile (c[] is dead now -> regs free)
        if (pf) {
            const float4* ml4 = (const float4*)(mlo + (size_t)(kt + 1) * TK);
            const float4* mh4 = (const float4*)(mhi + (size_t)(kt + 1) * TK);
            #pragma unroll
            for (int jg = 0; jg < 4; ++jg) {
                mcl[jg] = ml4[jg * 4 + qd];
                mch[jg] = mh4[jg * 4 + qd];
            }
        }

        // prefetch next V tile (regs)
        float4 vf0, vf1, vf2, vf3;
        if (pf) {
            const float* vp = vg + (size_t)(kt + 1) * TK * Dv;
            vf0 = *(const float4*)(vp + n0 * Dv + pc0);
            vf1 = *(const float4*)(vp + n0 * Dv + pc0 + 4);
            vf2 = *(const float4*)(vp + (n0 + 32) * Dv + pc0);
            vf3 = *(const float4*)(vp + (n0 + 32) * Dv + pc0 + 4);
        }

        // store prefetched K into next buffer
        if (pf) {
            sts16(KBn + so0, f2h2(kf0.x,kf0.y), f2h2(kf0.z,kf0.w), f2h2(kf1.x,kf1.y), f2h2(kf1.z,kf1.w));
            sts16(KBn + so1, f2h2(kf2.x,kf2.y), f2h2(kf2.z,kf2.w), f2h2(kf3.x,kf3.y), f2h2(kf3.z,kf3.w));
        }

        // ---- GEMM2: O(16x64) += P @ V  (x4 trans ldsm: two j-blocks) ----
        #pragma unroll
        for (int kb = 0; kb < 4; ++kb) {
            #pragma unroll
            for (int jp = 0; jp < 4; ++jp) {
                uint32_t b0, b1, b2, b3;
                ldsm4t(b0, b1, b2, b3,
                       VBc + swz(kb * 16 + l15, (2 * jp + grp) * 16));
                mma16816(o[2 * jp],     pa[kb], b0, b1);
                mma16816(o[2 * jp + 1], pa[kb], b2, b3);
            }
        }

        // store prefetched V into next buffer
        if (pf) {
            sts16(VBn + so0, f2h2(vf0.x,vf0.y), f2h2(vf0.z,vf0.w), f2h2(vf1.x,vf1.y), f2h2(vf1.z,vf1.w));
            sts16(VBn + so1, f2h2(vf2.x,vf2.y), f2h2(vf2.z,vf2.w), f2h2(vf3.x,vf3.y), f2h2(vf3.z,vf3.w));
        }

        __syncthreads();
    }

    // ---- normalizer quad-reduction ----
    rlo += __shfl_xor_sync(0xffffffffu, rlo, 1);
    rlo += __shfl_xor_sync(0xffffffffu, rlo, 2);
    rhi += __shfl_xor_sync(0xffffffffu, rhi, 1);
    rhi += __shfl_xor_sync(0xffffffffu, rhi, 2);
    const float il = 1.0f / fmaxf(rlo, 1.0f);
    const float ih = 1.0f / fmaxf(rhi, 1.0f);

    // ---- epilogue ----
    #pragma unroll
    for (int j = 0; j < 8; ++j) {
        float2 lo2, hi2;
        lo2.x = o[j][0] * il;  lo2.y = o[j][1] * il;
        hi2.x = o[j][2] * ih;  hi2.y = o[j][3] * ih;
        *(float2*)(olo + 8 * j + 2 * qd) = lo2;
        *(float2*)(ohi + 8 * j + 2 * qd) = hi2;
    }
}

extern "C" void kernel_launch(void* const* d_in, const int* in_sizes, int n_in,
                              void* d_out, int out_size)
{
    const float* q    = (const float*)d_in[0];
    const float* k    = (const float*)d_in[1];
    const float* v    = (const float*)d_in[2];
    const float* mask = (const float*)d_in[3];
    float* out        = (float*)d_out;

    dim3 grid(Sv / TQ, Bv * Hv);   // (16, 32) = 512 CTAs
    flashret_fp16_kernel<<<grid, NTH>>>(q, k, v, mask, out);
}

// round 7
// speedup vs baseline: 1.3340x; 1.3340x over previous
#include <cuda_runtime.h>
#include <cuda_fp16.h>
#include <cstdint>

// ---------------- problem constants ----------------
#define Bv   2
#define Hv   16
#define Sv   2048
#define Dv   64
#define TQ   128           // query rows per CTA (8 warps x 16 rows)
#define TK   64            // keys per tile
#define NT   (Sv / TK)     // 32 tiles
#define NTH  256
#define KVN  (Bv*Hv*Sv*Dv) // 4,194,304 elements per tensor

// fp16 scratch for K and V (converted once by prepass kernel)
__device__ __align__(16) uint4 g_kh[KVN / 8];   // 8 MB
__device__ __align__(16) uint4 g_vh[KVN / 8];   // 8 MB

// ---------------- helpers ----------------
__device__ __forceinline__ uint32_t smem_u32(const void* p) {
    uint32_t a;
    asm("{ .reg .u64 t; cvta.to.shared.u64 t, %1; cvt.u32.u64 %0, t; }" : "=r"(a) : "l"(p));
    return a;
}
__device__ __forceinline__ uint32_t f2h2(float x, float y) {
    __half2 h = __floats2half2_rn(x, y);
    return *reinterpret_cast<uint32_t*>(&h);
}
__device__ __forceinline__ void ldsm2(uint32_t& r0, uint32_t& r1, uint32_t a) {
    asm volatile("ldmatrix.sync.aligned.m8n8.x2.shared.b16 {%0,%1}, [%2];"
                 : "=r"(r0), "=r"(r1) : "r"(a));
}
__device__ __forceinline__ void ldsm2t(uint32_t& r0, uint32_t& r1, uint32_t a) {
    asm volatile("ldmatrix.sync.aligned.m8n8.x2.trans.shared.b16 {%0,%1}, [%2];"
                 : "=r"(r0), "=r"(r1) : "r"(a));
}
__device__ __forceinline__ void mma16816(float* c, const uint32_t* a, uint32_t b0, uint32_t b1) {
    asm volatile(
        "mma.sync.aligned.m16n8k16.row.col.f32.f16.f16.f32 "
        "{%0,%1,%2,%3}, {%4,%5,%6,%7}, {%8,%9}, {%0,%1,%2,%3};"
        : "+f"(c[0]), "+f"(c[1]), "+f"(c[2]), "+f"(c[3])
        : "r"(a[0]), "r"(a[1]), "r"(a[2]), "r"(a[3]), "r"(b0), "r"(b1));
}
// SW128 swizzle for a [64 rows][128B] fp16 tile
__device__ __forceinline__ uint32_t swz(int row, int cb) {
    return (uint32_t)(row * 128 + (cb ^ ((row & 7) << 4)));
}
__device__ __forceinline__ void cpasync16(uint32_t dst, const void* src) {
    asm volatile("cp.async.cg.shared.global [%0], [%1], 16;"
                 :: "r"(dst), "l"(src) : "memory");
}
#define CP_COMMIT()  asm volatile("cp.async.commit_group;" ::: "memory")
#define CP_WAIT2()   asm volatile("cp.async.wait_group 2;" ::: "memory")

// ---------------- prepass: fp32 K/V -> fp16 scratch ----------------
__global__ __launch_bounds__(256)
void convert_kv_kernel(const float* __restrict__ k, const float* __restrict__ v)
{
    int i = blockIdx.x * blockDim.x + threadIdx.x;   // one uint4 (8 halves) per thread
    const float4* k4 = (const float4*)k;
    const float4* v4 = (const float4*)v;
    float4 a0 = k4[2 * i], a1 = k4[2 * i + 1];
    float4 b0 = v4[2 * i], b1 = v4[2 * i + 1];
    uint4 ko, vo;
    ko.x = f2h2(a0.x, a0.y); ko.y = f2h2(a0.z, a0.w);
    ko.z = f2h2(a1.x, a1.y); ko.w = f2h2(a1.z, a1.w);
    vo.x = f2h2(b0.x, b0.y); vo.y = f2h2(b0.z, b0.w);
    vo.z = f2h2(b1.x, b1.y); vo.w = f2h2(b1.z, b1.w);
    g_kh[i] = ko;
    g_vh[i] = vo;
}

// ---------------- main kernel ----------------
__global__ __launch_bounds__(NTH, 2)
void flashret_fp16_kernel(const float* __restrict__ q,
                          const float* __restrict__ mask,
                          float* __restrict__ out)
{
    // K/V fp16 tiles, 4-stage ring each: 8 x 8KB = 64KB dynamic smem
    extern __shared__ __align__(1024) uint8_t smem[];
    const uint32_t sb = smem_u32(smem);

    const int tid  = threadIdx.x;
    const int warp = tid >> 5;
    const int lane = tid & 31;
    const int tq   = lane >> 2;
    const int qd   = lane & 3;
    const int R    = warp * 16;

    const int bh = blockIdx.y;
    const int qt = blockIdx.x;

    const size_t qrow = (size_t)bh * Sv + (size_t)qt * TQ + R + tq;
    const float* qlo = q + qrow * Dv;
    const float* qhi = qlo + 8 * Dv;
    const float* mlo = mask + qrow * (size_t)Sv;
    const float* mhi = mlo + (size_t)8 * Sv;
    float* olo = out + qrow * Dv;
    float* ohi = olo + 8 * Dv;
    const __half* khb = (const __half*)g_kh + (size_t)bh * Sv * Dv;
    const __half* vhb = (const __half*)g_vh + (size_t)bh * Sv * Dv;

    // producer mapping: rows n0, n0+32; 16B chunk c0 within 128B row
    const int n0 = tid >> 3, c0 = tid & 7;
    const uint32_t so0 = swz(n0, c0 * 16);
    const uint32_t so1 = swz(n0 + 32, c0 * 16);

    // ---- Q A-fragments straight from gmem ----
    uint32_t qa[4][4];
    #pragma unroll
    for (int kb = 0; kb < 4; ++kb) {
        float2 a0 = *(const float2*)(qlo + kb * 16 + 2 * qd);
        float2 a1 = *(const float2*)(qhi + kb * 16 + 2 * qd);
        float2 a2 = *(const float2*)(qlo + kb * 16 + 8 + 2 * qd);
        float2 a3 = *(const float2*)(qhi + kb * 16 + 8 + 2 * qd);
        qa[kb][0] = f2h2(a0.x, a0.y);
        qa[kb][1] = f2h2(a1.x, a1.y);
        qa[kb][2] = f2h2(a2.x, a2.y);
        qa[kb][3] = f2h2(a3.x, a3.y);
    }

    float o[8][4];
    #pragma unroll
    for (int j = 0; j < 8; ++j) { o[j][0] = o[j][1] = o[j][2] = o[j][3] = 0.0f; }
    float rlo = 0.0f, rhi = 0.0f;

    // ---- cp.async tile issue helper (4 x 16B per thread) ----
    auto issue_tile = [&](int kt) {
        const uint32_t KB = sb + (uint32_t)(kt & 3) * 8192;
        const uint32_t VB = sb + 32768 + (uint32_t)(kt & 3) * 8192;
        const __half* ks = khb + ((size_t)kt * TK + n0) * Dv + c0 * 8;
        const __half* vs = vhb + ((size_t)kt * TK + n0) * Dv + c0 * 8;
        cpasync16(KB + so0, ks);
        cpasync16(KB + so1, ks + 32 * Dv);
        cpasync16(VB + so0, vs);
        cpasync16(VB + so1, vs + 32 * Dv);
    };

    // ---- prologue: tiles 0,1 in flight; mask tile 0 in regs ----
    issue_tile(0); CP_COMMIT();
    issue_tile(1); CP_COMMIT();

    float2 mcl[8], mch[8];
    #pragma unroll
    for (int j = 0; j < 8; ++j) {
        mcl[j] = *(const float2*)(mlo + 8 * j + 2 * qd);
        mch[j] = *(const float2*)(mhi + 8 * j + 2 * qd);
    }

    const int lrow8  = lane & 7;
    const int lkhalf = ((lane >> 3) & 1) * 16;
    const int lrow16 = lane & 15;

    for (int kt = 0; kt < NT; ++kt) {
        if (kt + 2 < NT) issue_tile(kt + 2);
        CP_COMMIT();                 // always commit (possibly empty group)
        CP_WAIT2();                  // tile kt complete (own copies)
        __syncthreads();             // cross-thread visibility + WAR protection

        const uint32_t KBc = sb + (uint32_t)(kt & 3) * 8192;
        const uint32_t VBc = sb + 32768 + (uint32_t)(kt & 3) * 8192;
        const bool pf = (kt + 1) < NT;

        // ---- GEMM1: S(16x64) = Q @ K^T ----
        float c[8][4];
        #pragma unroll
        for (int j = 0; j < 8; ++j) { c[j][0] = c[j][1] = c[j][2] = c[j][3] = 0.0f; }
        #pragma unroll
        for (int j = 0; j < 8; ++j) {
            #pragma unroll
            for (int kb = 0; kb < 4; ++kb) {
                uint32_t b0, b1;
                ldsm2(b0, b1, KBc + swz(8 * j + lrow8, kb * 32 + lkhalf));
                mma16816(c[j], qa[kb], b0, b1);
            }
        }

        // ---- mask multiply + |.| + pack P A-frags (mask preloaded) ----
        uint32_t pa[4][4];
        #pragma unroll
        for (int j = 0; j < 8; ++j) {
            float2 am = mcl[j];
            float2 bm = mch[j];
            float p0 = c[j][0] * am.x;
            float p1 = c[j][1] * am.y;
            float p2 = c[j][2] * bm.x;
            float p3 = c[j][3] * bm.y;
            rlo += fabsf(p0) + fabsf(p1);
            rhi += fabsf(p2) + fabsf(p3);
            const int kb = j >> 1, h = (j & 1) << 1;
            pa[kb][h]     = f2h2(p0, p1);
            pa[kb][h + 1] = f2h2(p2, p3);
        }

        // prefetch next tile's mask (c[] dead -> regs free; hides DRAM latency)
        if (pf) {
            const float* ml = mlo + (size_t)(kt + 1) * TK;
            const float* mh = mhi + (size_t)(kt + 1) * TK;
            #pragma unroll
            for (int j = 0; j < 8; ++j) {
                mcl[j] = *(const float2*)(ml + 8 * j + 2 * qd);
                mch[j] = *(const float2*)(mh + 8 * j + 2 * qd);
            }
        }

        // ---- GEMM2: O(16x64) += P @ V ----
        #pragma unroll
        for (int j = 0; j < 8; ++j) {
            #pragma unroll
            for (int kb = 0; kb < 4; ++kb) {
                uint32_t b0, b1;
                ldsm2t(b0, b1, VBc + swz(kb * 16 + lrow16, j * 16));
                mma16816(o[j], pa[kb], b0, b1);
            }
        }
    }

    // ---- normalizer quad-reduction ----
    rlo += __shfl_xor_sync(0xffffffffu, rlo, 1);
    rlo += __shfl_xor_sync(0xffffffffu, rlo, 2);
    rhi += __shfl_xor_sync(0xffffffffu, rhi, 1);
    rhi += __shfl_xor_sync(0xffffffffu, rhi, 2);
    const float il = 1.0f / fmaxf(rlo, 1.0f);
    const float ih = 1.0f / fmaxf(rhi, 1.0f);

    // ---- epilogue ----
    #pragma unroll
    for (int j = 0; j < 8; ++j) {
        float2 lo2, hi2;
        lo2.x = o[j][0] * il;  lo2.y = o[j][1] * il;
        hi2.x = o[j][2] * ih;  hi2.y = o[j][3] * ih;
        *(float2*)(olo + 8 * j + 2 * qd) = lo2;
        *(float2*)(ohi + 8 * j + 2 * qd) = hi2;
    }
}

extern "C" void kernel_launch(void* const* d_in, const int* in_sizes, int n_in,
                              void* d_out, int out_size)
{
    const float* q    = (const float*)d_in[0];
    const float* k    = (const float*)d_in[1];
    const float* v    = (const float*)d_in[2];
    const float* mask = (const float*)d_in[3];
    float* out        = (float*)d_out;

    // prepass: fp32 K/V -> fp16 scratch (KVN/8 uint4 chunks)
    convert_kv_kernel<<<KVN / 8 / 256, 256>>>(k, v);

    cudaFuncSetAttribute(flashret_fp16_kernel,
                         cudaFuncAttributeMaxDynamicSharedMemorySize, 65536);
    dim3 grid(Sv / TQ, Bv * Hv);   // (16, 32) = 512 CTAs
    flashret_fp16_kernel<<<grid, NTH, 65536>>>(q, mask, out);
}

// round 9
// speedup vs baseline: 2.1422x; 1.6059x over previous
#include <cuda_runtime.h>
#include <cuda_fp16.h>
#include <cstdint>

// ---------------- problem constants ----------------
#define Bv   2
#define Hv   16
#define Sv   2048
#define Dv   64
#define TQ   128           // query rows per CTA (8 warps x 16 rows)
#define TK   64            // keys per tile
#define NT   (Sv / TK)     // 32 tiles
#define NTH  256
#define KVN  (Bv*Hv*Sv*Dv) // 4,194,304 elements per tensor

// fp16 scratch for K and V (converted once by prepass kernel)
__device__ __align__(16) uint4 g_kh[KVN / 8];   // 8 MB
__device__ __align__(16) uint4 g_vh[KVN / 8];   // 8 MB

// ---------------- smem layout (bytes), 2-stage everything ----------------
//  K slot s:  s*8192        (64 rows x 128B, SW128)
//  V slot s:  16384+s*8192
//  M slot s:  32768+s*32768 (128 rows x 256B, XOR-8B swizzled)
#define OFF_K(s)  ((uint32_t)(s)*8192u)
#define OFF_V(s)  (16384u + (uint32_t)(s)*8192u)
#define OFF_M(s)  (32768u + (uint32_t)(s)*32768u)
#define SMEM_TOT  98304

// ---------------- helpers ----------------
__device__ __forceinline__ uint32_t smem_u32(const void* p) {
    uint32_t a;
    asm("{ .reg .u64 t; cvta.to.shared.u64 t, %1; cvt.u32.u64 %0, t; }" : "=r"(a) : "l"(p));
    return a;
}
__device__ __forceinline__ uint32_t f2h2(float x, float y) {
    __half2 h = __floats2half2_rn(x, y);
    return *reinterpret_cast<uint32_t*>(&h);
}
__device__ __forceinline__ void ldsm2(uint32_t& r0, uint32_t& r1, uint32_t a) {
    asm volatile("ldmatrix.sync.aligned.m8n8.x2.shared.b16 {%0,%1}, [%2];"
                 : "=r"(r0), "=r"(r1) : "r"(a));
}
__device__ __forceinline__ void ldsm2t(uint32_t& r0, uint32_t& r1, uint32_t a) {
    asm volatile("ldmatrix.sync.aligned.m8n8.x2.trans.shared.b16 {%0,%1}, [%2];"
                 : "=r"(r0), "=r"(r1) : "r"(a));
}
__device__ __forceinline__ void mma16816(float* c, const uint32_t* a, uint32_t b0, uint32_t b1) {
    asm volatile(
        "mma.sync.aligned.m16n8k16.row.col.f32.f16.f16.f32 "
        "{%0,%1,%2,%3}, {%4,%5,%6,%7}, {%8,%9}, {%0,%1,%2,%3};"
        : "+f"(c[0]), "+f"(c[1]), "+f"(c[2]), "+f"(c[3])
        : "r"(a[0]), "r"(a[1]), "r"(a[2]), "r"(a[3]), "r"(b0), "r"(b1));
}
// SW128 swizzle for a [64 rows][128B] fp16 tile
__device__ __forceinline__ uint32_t swz(int row, int cb) {
    return (uint32_t)(row * 128 + (cb ^ ((row & 7) << 4)));
}
__device__ __forceinline__ void cpasync16(uint32_t dst, const void* src) {
    asm volatile("cp.async.cg.shared.global [%0], [%1], 16;"
                 :: "r"(dst), "l"(src) : "memory");
}
__device__ __forceinline__ float2 lds64(uint32_t a) {
    float2 v;
    asm volatile("ld.shared.v2.f32 {%0,%1}, [%2];" : "=f"(v.x), "=f"(v.y) : "r"(a));
    return v;
}
#define CP_COMMIT()  asm volatile("cp.async.commit_group;" ::: "memory")
#define CP_WAIT1()   asm volatile("cp.async.wait_group 1;" ::: "memory")

// ---------------- prepass: fp32 K/V -> fp16 scratch ----------------
__global__ __launch_bounds__(256)
void convert_kv_kernel(const float* __restrict__ k, const float* __restrict__ v)
{
    int i = blockIdx.x * blockDim.x + threadIdx.x;
    const float4* k4 = (const float4*)k;
    const float4* v4 = (const float4*)v;
    float4 a0 = k4[2 * i], a1 = k4[2 * i + 1];
    float4 b0 = v4[2 * i], b1 = v4[2 * i + 1];
    uint4 ko, vo;
    ko.x = f2h2(a0.x, a0.y); ko.y = f2h2(a0.z, a0.w);
    ko.z = f2h2(a1.x, a1.y); ko.w = f2h2(a1.z, a1.w);
    vo.x = f2h2(b0.x, b0.y); vo.y = f2h2(b0.z, b0.w);
    vo.z = f2h2(b1.x, b1.y); vo.w = f2h2(b1.z, b1.w);
    g_kh[i] = ko;
    g_vh[i] = vo;
}

// ---------------- main kernel ----------------
__global__ __launch_bounds__(NTH, 2)
void flashret_fp16_kernel(const float* __restrict__ q,
                          const float* __restrict__ mask,
                          float* __restrict__ out)
{
    extern __shared__ __align__(1024) uint8_t smem[];
    const uint32_t sb = smem_u32(smem);

    const int tid  = threadIdx.x;
    const int warp = tid >> 5;
    const int lane = tid & 31;
    const int tq   = lane >> 2;
    const int qd   = lane & 3;
    const int R    = warp * 16;

    const int bh = blockIdx.y;
    const int qt = blockIdx.x;

    const size_t qrow = (size_t)bh * Sv + (size_t)qt * TQ + R + tq;
    const float* qlo = q + qrow * Dv;
    const float* qhi = qlo + 8 * Dv;
    float* olo = out + qrow * Dv;
    float* ohi = olo + 8 * Dv;
    const __half* khb = (const __half*)g_kh + (size_t)bh * Sv * Dv;
    const __half* vhb = (const __half*)g_vh + (size_t)bh * Sv * Dv;

    // KV producer mapping: rows n0, n0+32; 16B chunk c0 within 128B row
    const int n0 = tid >> 3, c0 = tid & 7;
    const uint32_t so0 = swz(n0, c0 * 16);
    const uint32_t so1 = swz(n0 + 32, c0 * 16);

    // Mask producer mapping: thread covers rows mrow0+16i (i=0..7), 16B chunk m
    const int mrow0 = tid >> 4;              // 0..15
    const int mm    = tid & 15;              // 16B chunk within 256B row
    const uint32_t mswz = (uint32_t)((mm ^ (2 * (mrow0 & 7))) * 16);
    const float* mCTA = mask + ((size_t)bh * Sv + (size_t)qt * TQ) * (size_t)Sv;
    const float* msrc0 = mCTA + (size_t)mrow0 * Sv + mm * 4;
    const uint32_t mdst0 = (uint32_t)(mrow0 * 256) + mswz;

    // ---- Q A-fragments straight from gmem ----
    uint32_t qa[4][4];
    #pragma unroll
    for (int kb = 0; kb < 4; ++kb) {
        float2 a0 = *(const float2*)(qlo + kb * 16 + 2 * qd);
        float2 a1 = *(const float2*)(qhi + kb * 16 + 2 * qd);
        float2 a2 = *(const float2*)(qlo + kb * 16 + 8 + 2 * qd);
        float2 a3 = *(const float2*)(qhi + kb * 16 + 8 + 2 * qd);
        qa[kb][0] = f2h2(a0.x, a0.y);
        qa[kb][1] = f2h2(a1.x, a1.y);
        qa[kb][2] = f2h2(a2.x, a2.y);
        qa[kb][3] = f2h2(a3.x, a3.y);
    }

    float o[8][4];
    #pragma unroll
    for (int j = 0; j < 8; ++j) { o[j][0] = o[j][1] = o[j][2] = o[j][3] = 0.0f; }
    float rlo = 0.0f, rhi = 0.0f;

    // ---- async issue helpers ----
    auto issue_kv = [&](int kt) {
        const uint32_t KB = sb + OFF_K(kt & 1);
        const uint32_t VB = sb + OFF_V(kt & 1);
        const __half* ks = khb + ((size_t)kt * TK + n0) * Dv + c0 * 8;
        const __half* vs = vhb + ((size_t)kt * TK + n0) * Dv + c0 * 8;
        cpasync16(KB + so0, ks);
        cpasync16(KB + so1, ks + 32 * Dv);
        cpasync16(VB + so0, vs);
        cpasync16(VB + so1, vs + 32 * Dv);
    };
    auto issue_mask = [&](int kt) {
        const uint32_t MB = sb + OFF_M(kt & 1) + mdst0;
        const float* ms = msrc0 + (size_t)kt * TK;
        #pragma unroll
        for (int i = 0; i < 8; ++i)
            cpasync16(MB + (uint32_t)(i * 16 * 256), ms + (size_t)i * 16 * Sv);
    };

    // prologue: tile 0 in flight
    issue_kv(0);
    issue_mask(0);
    CP_COMMIT();

    const int lrow8  = lane & 7;
    const int lkhalf = ((lane >> 3) & 1) * 16;
    const int lrow16 = lane & 15;

    for (int kt = 0; kt < NT; ++kt) {
        __syncthreads();                 // WAR: prev-iter reads of slot (kt+1)&1 done
        if (kt + 1 < NT) { issue_kv(kt + 1); issue_mask(kt + 1); }
        CP_COMMIT();
        CP_WAIT1();                      // tile kt (KV + mask) complete
        __syncthreads();                 // cross-thread visibility

        const uint32_t KBc = sb + OFF_K(kt & 1);
        const uint32_t VBc = sb + OFF_V(kt & 1);
        const uint32_t mb  = sb + OFF_M(kt & 1) + (uint32_t)((R + tq) * 256) + (uint32_t)(qd * 8);

        // ---- GEMM1: S(16x64) = Q @ K^T ----
        float c[8][4];
        #pragma unroll
        for (int j = 0; j < 8; ++j) { c[j][0] = c[j][1] = c[j][2] = c[j][3] = 0.0f; }
        #pragma unroll
        for (int j = 0; j < 8; ++j) {
            #pragma unroll
            for (int kb = 0; kb < 4; ++kb) {
                uint32_t b0, b1;
                ldsm2(b0, b1, KBc + swz(8 * j + lrow8, kb * 32 + lkhalf));
                mma16816(c[j], qa[kb], b0, b1);
            }
        }

        // ---- mask multiply (swizzled smem) + |.| + pack P A-frags ----
        uint32_t pa[4][4];
        #pragma unroll
        for (int j = 0; j < 8; ++j) {
            const uint32_t ma = mb + (uint32_t)((j ^ tq) << 5);
            float2 am = lds64(ma);          // row R+tq,   cols 8j+2qd..+1
            float2 bm = lds64(ma + 2048);   // row R+tq+8, same swizzle (row&7 == tq)
            float p0 = c[j][0] * am.x;
            float p1 = c[j][1] * am.y;
            float p2 = c[j][2] * bm.x;
            float p3 = c[j][3] * bm.y;
            rlo += fabsf(p0) + fabsf(p1);
            rhi += fabsf(p2) + fabsf(p3);
            const int kb = j >> 1, h = (j & 1) << 1;
            pa[kb][h]     = f2h2(p0, p1);
            pa[kb][h + 1] = f2h2(p2, p3);
        }

        // ---- GEMM2: O(16x64) += P @ V ----
        #pragma unroll
        for (int j = 0; j < 8; ++j) {
            #pragma unroll
            for (int kb = 0; kb < 4; ++kb) {
                uint32_t b0, b1;
                ldsm2t(b0, b1, VBc + swz(kb * 16 + lrow16, j * 16));
                mma16816(o[j], pa[kb], b0, b1);
            }
        }
    }

    // ---- normalizer quad-reduction ----
    rlo += __shfl_xor_sync(0xffffffffu, rlo, 1);
    rlo += __shfl_xor_sync(0xffffffffu, rlo, 2);
    rhi += __shfl_xor_sync(0xffffffffu, rhi, 1);
    rhi += __shfl_xor_sync(0xffffffffu, rhi, 2);
    const float il = 1.0f / fmaxf(rlo, 1.0f);
    const float ih = 1.0f / fmaxf(rhi, 1.0f);

    // ---- epilogue ----
    #pragma unroll
    for (int j = 0; j < 8; ++j) {
        float2 lo2, hi2;
        lo2.x = o[j][0] * il;  lo2.y = o[j][1] * il;
        hi2.x = o[j][2] * ih;  hi2.y = o[j][3] * ih;
        *(float2*)(olo + 8 * j + 2 * qd) = lo2;
        *(float2*)(ohi + 8 * j + 2 * qd) = hi2;
    }
}

extern "C" void kernel_launch(void* const* d_in, const int* in_sizes, int n_in,
                              void* d_out, int out_size)
{
    const float* q    = (const float*)d_in[0];
    const float* k    = (const float*)d_in[1];
    const float* v    = (const float*)d_in[2];
    const float* mask = (const float*)d_in[3];
    float* out        = (float*)d_out;

    convert_kv_kernel<<<KVN / 8 / 256, 256>>>(k, v);

    cudaFuncSetAttribute(flashret_fp16_kernel,
                         cudaFuncAttributeMaxDynamicSharedMemorySize, SMEM_TOT);
    dim3 grid(Sv / TQ, Bv * Hv);   // (16, 32) = 512 CTAs
    flashret_fp16_kernel<<<grid, NTH, SMEM_TOT>>>(q, mask, out);
}